// round 9
// baseline (speedup 1.0000x reference)
#include <cuda_runtime.h>

#define D 128
#define MAX_NODES 50048
#define MAX_E     1048576
#define BK 32
#define SAP 132           // padded row stride for A smem tile
#define SWP 68            // padded row stride for W-half smem tile
#define SCAN_B 256
#define MAX_SCAN_BLOCKS 256

// Scratch (allocation-free rule: __device__ globals)
__device__ float g_fp[MAX_NODES * D];      // F' = feature @ W^T
__device__ int   g_count[MAX_NODES];
__device__ int   g_excl[MAX_NODES];
__device__ int   g_bsum[MAX_SCAN_BLOCKS];
__device__ int   g_boff[MAX_SCAN_BLOCKS];
__device__ int   g_start[MAX_NODES + 1];
__device__ int   g_cursor[MAX_NODES];
__device__ int2  g_edges[MAX_E];           // packed {src, w_bits} binned by dst

// ---------------------------------------------------------------------------
// binning chain
// ---------------------------------------------------------------------------
__global__ void zero_count_kernel(int N) {
    int i = blockIdx.x * blockDim.x + threadIdx.x;
    if (i < N) g_count[i] = 0;
}

__global__ void hist_kernel(const int* __restrict__ dst, int E) {
    int e = blockIdx.x * blockDim.x + threadIdx.x;
    if (e < E) atomicAdd(&g_count[dst[e]], 1);
}

__global__ void scan1_kernel(int N) {
    __shared__ int sh[SCAN_B];
    int t = threadIdx.x;
    int i = blockIdx.x * SCAN_B + t;
    int v = (i < N) ? g_count[i] : 0;
    sh[t] = v;
    __syncthreads();
#pragma unroll
    for (int off = 1; off < SCAN_B; off <<= 1) {
        int u = (t >= off) ? sh[t - off] : 0;
        __syncthreads();
        sh[t] += u;
        __syncthreads();
    }
    if (i < N) g_excl[i] = sh[t] - v;
    if (t == SCAN_B - 1) g_bsum[blockIdx.x] = sh[SCAN_B - 1];
}

__global__ void scan2_kernel(int NB, int N) {
    __shared__ int sh[MAX_SCAN_BLOCKS];
    int t = threadIdx.x;
    int v = (t < NB) ? g_bsum[t] : 0;
    sh[t] = v;
    __syncthreads();
#pragma unroll
    for (int off = 1; off < MAX_SCAN_BLOCKS; off <<= 1) {
        int u = (t >= off) ? sh[t - off] : 0;
        __syncthreads();
        sh[t] += u;
        __syncthreads();
    }
    if (t < NB) g_boff[t] = sh[t] - v;
    if (t == MAX_SCAN_BLOCKS - 1) g_start[N] = sh[MAX_SCAN_BLOCKS - 1];
}

__global__ void scan3_kernel(int N) {
    int i = blockIdx.x * blockDim.x + threadIdx.x;
    if (i < N) {
        int s = g_excl[i] + g_boff[i >> 8];
        g_start[i]  = s;
        g_cursor[i] = s;
    }
}

__global__ void permute_kernel(const int* __restrict__ src,
                               const int* __restrict__ dst,
                               const float* __restrict__ w,
                               int E) {
    int e = blockIdx.x * blockDim.x + threadIdx.x;
    if (e < E) {
        int pos = atomicAdd(&g_cursor[dst[e]], 1);
        g_edges[pos] = make_int2(src[e], __float_as_int(w[e]));
    }
}

// ---------------------------------------------------------------------------
// GEMM half: F'[:, c0..c0+64) = feature @ W[c0..c0+64, :]^T
// block = 128 rows x 64 cols, 256 threads, 8x4 microtile.
// ---------------------------------------------------------------------------
__global__ void gemm_half_kernel(const float* __restrict__ A,
                                 const float* __restrict__ Wm,
                                 int M, int c0) {
    __shared__ float sA[BK * SAP];   // sA[k][m], m 0..127
    __shared__ float sW[BK * SWP];   // sW[k][j], j 0..63

    int tid = threadIdx.x;
    int tx = tid & 15;        // col group: 4 cols each
    int ty = tid >> 4;        // row group: 8 rows each
    int br = blockIdx.x * 128;

    float acc[8][4];
#pragma unroll
    for (int i = 0; i < 8; i++)
#pragma unroll
        for (int j = 0; j < 4; j++) acc[i][j] = 0.f;

    for (int kt = 0; kt < D; kt += BK) {
        // A tile: 128 x 32 = 1024 float4, 4 per thread
#pragma unroll
        for (int it = 0; it < 4; it++) {
            int idx4 = tid + it * 256;
            int m  = idx4 >> 3;
            int k  = (idx4 & 7) * 4;
            float4 va = make_float4(0.f, 0.f, 0.f, 0.f);
            if (br + m < M)
                va = *(const float4*)(A + (size_t)(br + m) * D + kt + k);
            sA[(k + 0) * SAP + m] = va.x;
            sA[(k + 1) * SAP + m] = va.y;
            sA[(k + 2) * SAP + m] = va.z;
            sA[(k + 3) * SAP + m] = va.w;
        }
        // W half tile: 64 x 32 = 512 float4, 2 per thread
#pragma unroll
        for (int it = 0; it < 2; it++) {
            int idx4 = tid + it * 256;
            int j  = idx4 >> 3;
            int k  = (idx4 & 7) * 4;
            float4 vw = *(const float4*)(Wm + (size_t)(c0 + j) * D + kt + k);
            sW[(k + 0) * SWP + j] = vw.x;
            sW[(k + 1) * SWP + j] = vw.y;
            sW[(k + 2) * SWP + j] = vw.z;
            sW[(k + 3) * SWP + j] = vw.w;
        }
        __syncthreads();

#pragma unroll
        for (int k = 0; k < BK; k++) {
            float a[8], wr[4];
            *(float4*)(a)      = *(const float4*)&sA[k * SAP + ty * 8];
            *(float4*)(a + 4)  = *(const float4*)&sA[k * SAP + ty * 8 + 4];
            *(float4*)(wr)     = *(const float4*)&sW[k * SWP + tx * 4];
#pragma unroll
            for (int i = 0; i < 8; i++)
#pragma unroll
                for (int j = 0; j < 4; j++)
                    acc[i][j] += a[i] * wr[j];
        }
        __syncthreads();
    }

#pragma unroll
    for (int i = 0; i < 8; i++) {
        int m = br + ty * 8 + i;
        if (m < M) {
            float* op = g_fp + (size_t)m * D + c0 + tx * 4;
            *(float4*)op = *(const float4*)&acc[i][0];
        }
    }
}

// ---------------------------------------------------------------------------
// Aggregate half + epilogue: warp per node, lane covers 2 floats of 64 cols.
// out[n, c0..c0+64) = relu(sum w_e * F'[src_e, c0..c0+64) + b[c0..])
// ---------------------------------------------------------------------------
__global__ void aggregate_half_kernel(const float* __restrict__ bias,
                                      float* __restrict__ out,
                                      int N, int c0) {
    int t = blockIdx.x * blockDim.x + threadIdx.x;
    int n = t >> 5;
    if (n >= N) return;
    int lane = t & 31;
    int col = c0 + lane * 2;

    int beg = g_start[n];
    int end = g_start[n + 1];

    float ax = 0.f, ay = 0.f;
    int i = beg;
    for (; i + 3 < end; i += 4) {
        int2 p0 = __ldg(&g_edges[i]);
        int2 p1 = __ldg(&g_edges[i + 1]);
        int2 p2 = __ldg(&g_edges[i + 2]);
        int2 p3 = __ldg(&g_edges[i + 3]);
        float w0 = __int_as_float(p0.y);
        float w1 = __int_as_float(p1.y);
        float w2 = __int_as_float(p2.y);
        float w3 = __int_as_float(p3.y);
        float2 v0 = *(const float2*)(g_fp + (size_t)p0.x * D + col);
        float2 v1 = *(const float2*)(g_fp + (size_t)p1.x * D + col);
        float2 v2 = *(const float2*)(g_fp + (size_t)p2.x * D + col);
        float2 v3 = *(const float2*)(g_fp + (size_t)p3.x * D + col);
        ax += v0.x * w0 + v1.x * w1 + v2.x * w2 + v3.x * w3;
        ay += v0.y * w0 + v1.y * w1 + v2.y * w2 + v3.y * w3;
    }
    for (; i < end; i++) {
        int2 p0 = __ldg(&g_edges[i]);
        float w0 = __int_as_float(p0.y);
        float2 v0 = *(const float2*)(g_fp + (size_t)p0.x * D + col);
        ax += v0.x * w0;
        ay += v0.y * w0;
    }

    float2 b2 = *(const float2*)(bias + col);
    ax = fmaxf(ax + b2.x, 0.f);
    ay = fmaxf(ay + b2.y, 0.f);

    *(float2*)(out + (size_t)n * D + col) = make_float2(ax, ay);
}

// ---------------------------------------------------------------------------
// Launch: 2-stage pipeline.
//   side:  GEMM_h1 -> GEMM_h2
//   main:  binning -> (wait h1) agg_h1 -> (wait h2) agg_h2
// ---------------------------------------------------------------------------
extern "C" void kernel_launch(void* const* d_in, const int* in_sizes, int n_in,
                              void* d_out, int out_size) {
    const float* feature = (const float*)d_in[0];
    const int*   src     = (const int*)d_in[1];
    const int*   dst     = (const int*)d_in[2];
    const float* w       = (const float*)d_in[3];
    const float* Wm      = (const float*)d_in[4];
    const float* bias    = (const float*)d_in[5];
    float*       out     = (float*)d_out;

    int M = in_sizes[0] / D;
    int E = in_sizes[1];
    if (E > MAX_E) E = MAX_E;

    static cudaStream_t s2 = nullptr;
    static cudaEvent_t evFork = nullptr, evG1 = nullptr, evG2 = nullptr;
    if (s2 == nullptr) {
        cudaStreamCreateWithFlags(&s2, cudaStreamNonBlocking);
        cudaEventCreateWithFlags(&evFork, cudaEventDisableTiming);
        cudaEventCreateWithFlags(&evG1, cudaEventDisableTiming);
        cudaEventCreateWithFlags(&evG2, cudaEventDisableTiming);
    }

    int gemm_grid = (M + 127) / 128;

    // Fork GEMM halves onto side stream
    cudaEventRecord(evFork, 0);
    cudaStreamWaitEvent(s2, evFork, 0);
    gemm_half_kernel<<<gemm_grid, 256, 0, s2>>>(feature, Wm, M, 0);
    cudaEventRecord(evG1, s2);
    gemm_half_kernel<<<gemm_grid, 256, 0, s2>>>(feature, Wm, M, 64);
    cudaEventRecord(evG2, s2);

    // Main stream: binning chain
    int NB = (M + SCAN_B - 1) / SCAN_B;
    zero_count_kernel<<<(M + 255) / 256, 256>>>(M);
    hist_kernel<<<(E + 255) / 256, 256>>>(dst, E);
    scan1_kernel<<<NB, SCAN_B>>>(M);
    scan2_kernel<<<1, MAX_SCAN_BLOCKS>>>(NB, M);
    scan3_kernel<<<(M + 255) / 256, 256>>>(M);
    permute_kernel<<<(E + 255) / 256, 256>>>(src, dst, w, E);

    // Pipelined aggregate halves
    long long agg_threads = (long long)M * 32;
    int agg_grid = (int)((agg_threads + 255) / 256);

    cudaStreamWaitEvent(0, evG1, 0);
    aggregate_half_kernel<<<agg_grid, 256>>>(bias, out, M, 0);
    cudaStreamWaitEvent(0, evG2, 0);
    aggregate_half_kernel<<<agg_grid, 256>>>(bias, out, M, 64);
}

// round 10
// speedup vs baseline: 1.2502x; 1.2502x over previous
#include <cuda_runtime.h>
#include <cuda_fp16.h>

#define D 128
#define MAX_NODES 50048
#define MAX_E     1048576
#define BK 32
#define SAP 132
#define SCAN_B 256
#define MAX_SCAN_BLOCKS 256

// Scratch (allocation-free rule: __device__ globals)
__device__ __half g_fph[MAX_NODES * D];    // F' = feature @ W^T, fp16 storage
__device__ int   g_count[MAX_NODES];
__device__ int   g_excl[MAX_NODES];
__device__ int   g_bsum[MAX_SCAN_BLOCKS];
__device__ int   g_boff[MAX_SCAN_BLOCKS];
__device__ int   g_start[MAX_NODES + 1];
__device__ int   g_cursor[MAX_NODES];
__device__ int2  g_edges[MAX_E];           // packed {src, w_bits} binned by dst

// ---------------------------------------------------------------------------
// binning chain (unchanged from R8)
// ---------------------------------------------------------------------------
__global__ void zero_count_kernel(int N) {
    int i = blockIdx.x * blockDim.x + threadIdx.x;
    if (i < N) g_count[i] = 0;
}

__global__ void hist_kernel(const int* __restrict__ dst, int E) {
    int e = blockIdx.x * blockDim.x + threadIdx.x;
    if (e < E) atomicAdd(&g_count[dst[e]], 1);
}

__global__ void scan1_kernel(int N) {
    __shared__ int sh[SCAN_B];
    int t = threadIdx.x;
    int i = blockIdx.x * SCAN_B + t;
    int v = (i < N) ? g_count[i] : 0;
    sh[t] = v;
    __syncthreads();
#pragma unroll
    for (int off = 1; off < SCAN_B; off <<= 1) {
        int u = (t >= off) ? sh[t - off] : 0;
        __syncthreads();
        sh[t] += u;
        __syncthreads();
    }
    if (i < N) g_excl[i] = sh[t] - v;
    if (t == SCAN_B - 1) g_bsum[blockIdx.x] = sh[SCAN_B - 1];
}

__global__ void scan2_kernel(int NB, int N) {
    __shared__ int sh[MAX_SCAN_BLOCKS];
    int t = threadIdx.x;
    int v = (t < NB) ? g_bsum[t] : 0;
    sh[t] = v;
    __syncthreads();
#pragma unroll
    for (int off = 1; off < MAX_SCAN_BLOCKS; off <<= 1) {
        int u = (t >= off) ? sh[t - off] : 0;
        __syncthreads();
        sh[t] += u;
        __syncthreads();
    }
    if (t < NB) g_boff[t] = sh[t] - v;
    if (t == MAX_SCAN_BLOCKS - 1) g_start[N] = sh[MAX_SCAN_BLOCKS - 1];
}

__global__ void scan3_kernel(int N) {
    int i = blockIdx.x * blockDim.x + threadIdx.x;
    if (i < N) {
        int s = g_excl[i] + g_boff[i >> 8];
        g_start[i]  = s;
        g_cursor[i] = s;
    }
}

__global__ void permute_kernel(const int* __restrict__ src,
                               const int* __restrict__ dst,
                               const float* __restrict__ w,
                               int E) {
    int e = blockIdx.x * blockDim.x + threadIdx.x;
    if (e < E) {
        int pos = atomicAdd(&g_cursor[dst[e]], 1);
        g_edges[pos] = make_int2(src[e], __float_as_int(w[e]));
    }
}

// ---------------------------------------------------------------------------
// GEMM: F' = feature @ W^T, fp32 math, fp16 output store (side stream)
// ---------------------------------------------------------------------------
__global__ void gemm_kernel(const float* __restrict__ A,
                            const float* __restrict__ Wm,
                            int M) {
    __shared__ float sA[BK * SAP];
    __shared__ float sW[BK * SAP];

    int tid = threadIdx.x;
    int tx = tid & 15;
    int ty = tid >> 4;
    int br = blockIdx.x * 128;

    float acc[8][8];
#pragma unroll
    for (int i = 0; i < 8; i++)
#pragma unroll
        for (int j = 0; j < 8; j++) acc[i][j] = 0.f;

    for (int kt = 0; kt < D; kt += BK) {
#pragma unroll
        for (int it = 0; it < 4; it++) {
            int idx4 = tid + it * 256;
            int m  = idx4 >> 3;
            int k  = (idx4 & 7) * 4;

            float4 va = make_float4(0.f, 0.f, 0.f, 0.f);
            if (br + m < M)
                va = *(const float4*)(A + (size_t)(br + m) * D + kt + k);
            sA[(k + 0) * SAP + m] = va.x;
            sA[(k + 1) * SAP + m] = va.y;
            sA[(k + 2) * SAP + m] = va.z;
            sA[(k + 3) * SAP + m] = va.w;

            float4 vw = *(const float4*)(Wm + m * D + kt + k);
            sW[(k + 0) * SAP + m] = vw.x;
            sW[(k + 1) * SAP + m] = vw.y;
            sW[(k + 2) * SAP + m] = vw.z;
            sW[(k + 3) * SAP + m] = vw.w;
        }
        __syncthreads();

#pragma unroll
        for (int k = 0; k < BK; k++) {
            float a[8], wr[8];
            *(float4*)(a)      = *(const float4*)&sA[k * SAP + ty * 8];
            *(float4*)(a + 4)  = *(const float4*)&sA[k * SAP + ty * 8 + 4];
            *(float4*)(wr)     = *(const float4*)&sW[k * SAP + tx * 8];
            *(float4*)(wr + 4) = *(const float4*)&sW[k * SAP + tx * 8 + 4];
#pragma unroll
            for (int i = 0; i < 8; i++)
#pragma unroll
                for (int j = 0; j < 8; j++)
                    acc[i][j] += a[i] * wr[j];
        }
        __syncthreads();
    }

    // fp16 epilogue: 8 halves = 16B per row-fragment, coalesced
#pragma unroll
    for (int i = 0; i < 8; i++) {
        int m = br + ty * 8 + i;
        if (m < M) {
            __half2 h[4];
            h[0] = __floats2half2_rn(acc[i][0], acc[i][1]);
            h[1] = __floats2half2_rn(acc[i][2], acc[i][3]);
            h[2] = __floats2half2_rn(acc[i][4], acc[i][5]);
            h[3] = __floats2half2_rn(acc[i][6], acc[i][7]);
            *(uint2*)(g_fph + (size_t)m * D + tx * 8)     = *(uint2*)&h[0];
            *(uint2*)(g_fph + (size_t)m * D + tx * 8 + 4) = *(uint2*)&h[2];
        }
    }
}

// ---------------------------------------------------------------------------
// Aggregate + epilogue: warp per node, lane covers 4 cols (8B fp16 load/edge).
// 256B per warp per edge (half of fp32).  fp32 accumulation.
// out[n] = relu(sum w_e * F'[src_e] + b)
// ---------------------------------------------------------------------------
__global__ void aggregate_out_kernel(const float* __restrict__ bias,
                                     float* __restrict__ out,
                                     int N) {
    int t = blockIdx.x * blockDim.x + threadIdx.x;
    int n = t >> 5;
    if (n >= N) return;
    int lane = t & 31;
    int col = lane * 4;

    int beg = g_start[n];
    int end = g_start[n + 1];

    float4 acc = make_float4(0.f, 0.f, 0.f, 0.f);
    int i = beg;
    for (; i + 3 < end; i += 4) {
        int2 p0 = __ldg(&g_edges[i]);
        int2 p1 = __ldg(&g_edges[i + 1]);
        int2 p2 = __ldg(&g_edges[i + 2]);
        int2 p3 = __ldg(&g_edges[i + 3]);
        uint2 u0 = *(const uint2*)(g_fph + (size_t)p0.x * D + col);
        uint2 u1 = *(const uint2*)(g_fph + (size_t)p1.x * D + col);
        uint2 u2 = *(const uint2*)(g_fph + (size_t)p2.x * D + col);
        uint2 u3 = *(const uint2*)(g_fph + (size_t)p3.x * D + col);
        float w0 = __int_as_float(p0.y);
        float w1 = __int_as_float(p1.y);
        float w2 = __int_as_float(p2.y);
        float w3 = __int_as_float(p3.y);

        float2 a0 = __half22float2(*(__half2*)&u0.x), b0 = __half22float2(*(__half2*)&u0.y);
        float2 a1 = __half22float2(*(__half2*)&u1.x), b1 = __half22float2(*(__half2*)&u1.y);
        float2 a2 = __half22float2(*(__half2*)&u2.x), b2 = __half22float2(*(__half2*)&u2.y);
        float2 a3 = __half22float2(*(__half2*)&u3.x), b3 = __half22float2(*(__half2*)&u3.y);

        acc.x += a0.x * w0 + a1.x * w1 + a2.x * w2 + a3.x * w3;
        acc.y += a0.y * w0 + a1.y * w1 + a2.y * w2 + a3.y * w3;
        acc.z += b0.x * w0 + b1.x * w1 + b2.x * w2 + b3.x * w3;
        acc.w += b0.y * w0 + b1.y * w1 + b2.y * w2 + b3.y * w3;
    }
    for (; i < end; i++) {
        int2 p0 = __ldg(&g_edges[i]);
        uint2 u0 = *(const uint2*)(g_fph + (size_t)p0.x * D + col);
        float w0 = __int_as_float(p0.y);
        float2 a0 = __half22float2(*(__half2*)&u0.x), b0 = __half22float2(*(__half2*)&u0.y);
        acc.x += a0.x * w0;
        acc.y += a0.y * w0;
        acc.z += b0.x * w0;
        acc.w += b0.y * w0;
    }

    float4 b4 = __ldg((const float4*)(bias + col));
    acc.x = fmaxf(acc.x + b4.x, 0.f);
    acc.y = fmaxf(acc.y + b4.y, 0.f);
    acc.z = fmaxf(acc.z + b4.z, 0.f);
    acc.w = fmaxf(acc.w + b4.w, 0.f);

    *(float4*)(out + (size_t)n * D + col) = acc;
}

// ---------------------------------------------------------------------------
// Launch: fork-join (R8 structure).
// ---------------------------------------------------------------------------
extern "C" void kernel_launch(void* const* d_in, const int* in_sizes, int n_in,
                              void* d_out, int out_size) {
    const float* feature = (const float*)d_in[0];
    const int*   src     = (const int*)d_in[1];
    const int*   dst     = (const int*)d_in[2];
    const float* w       = (const float*)d_in[3];
    const float* Wm      = (const float*)d_in[4];
    const float* bias    = (const float*)d_in[5];
    float*       out     = (float*)d_out;

    int M = in_sizes[0] / D;
    int E = in_sizes[1];
    if (E > MAX_E) E = MAX_E;

    static cudaStream_t s2 = nullptr;
    static cudaEvent_t evFork = nullptr, evGemm = nullptr;
    if (s2 == nullptr) {
        cudaStreamCreateWithFlags(&s2, cudaStreamNonBlocking);
        cudaEventCreateWithFlags(&evFork, cudaEventDisableTiming);
        cudaEventCreateWithFlags(&evGemm, cudaEventDisableTiming);
    }

    // Fork: GEMM on side stream
    cudaEventRecord(evFork, 0);
    cudaStreamWaitEvent(s2, evFork, 0);
    gemm_kernel<<<(M + 127) / 128, 256, 0, s2>>>(feature, Wm, M);
    cudaEventRecord(evGemm, s2);

    // Main stream: binning chain
    int NB = (M + SCAN_B - 1) / SCAN_B;
    zero_count_kernel<<<(M + 255) / 256, 256>>>(M);
    hist_kernel<<<(E + 255) / 256, 256>>>(dst, E);
    scan1_kernel<<<NB, SCAN_B>>>(M);
    scan2_kernel<<<1, MAX_SCAN_BLOCKS>>>(NB, M);
    scan3_kernel<<<(M + 255) / 256, 256>>>(M);
    permute_kernel<<<(E + 255) / 256, 256>>>(src, dst, w, E);

    // Join, then aggregate + epilogue
    cudaStreamWaitEvent(0, evGemm, 0);
    long long agg_threads = (long long)M * 32;
    aggregate_out_kernel<<<(int)((agg_threads + 255) / 256), 256>>>(bias, out, M);
}

// round 11
// speedup vs baseline: 1.4381x; 1.1503x over previous
#include <cuda_runtime.h>
#include <cuda_fp16.h>
#include <cstdint>

#define D 128
#define MAX_NODES 50048
#define MAX_E     1048576
#define SCAN_B 256
#define MAX_SCAN_BLOCKS 256
#define GP 20              // uint32 (half2) row stride in GEMM smem (conflict-free frags)

// Scratch (allocation-free rule: __device__ globals)
__device__ __half g_fph[MAX_NODES * D];    // F' = feature @ W^T, fp16 storage
__device__ int   g_count[MAX_NODES];       // zero-initialized at load; re-zeroed by scan3
__device__ int   g_excl[MAX_NODES];
__device__ int   g_bsum[MAX_SCAN_BLOCKS];
__device__ int   g_boff[MAX_SCAN_BLOCKS];
__device__ int   g_start[MAX_NODES + 1];
__device__ int   g_cursor[MAX_NODES];
__device__ int2  g_edges[MAX_E];           // packed {src, w_bits} binned by dst

// ---------------------------------------------------------------------------
// binning chain
// ---------------------------------------------------------------------------
__global__ void hist_kernel(const int* __restrict__ dst, int E) {
    int e = blockIdx.x * blockDim.x + threadIdx.x;
    if (e < E) atomicAdd(&g_count[dst[e]], 1);
}

__global__ void scan1_kernel(int N) {
    __shared__ int sh[SCAN_B];
    int t = threadIdx.x;
    int i = blockIdx.x * SCAN_B + t;
    int v = (i < N) ? g_count[i] : 0;
    sh[t] = v;
    __syncthreads();
#pragma unroll
    for (int off = 1; off < SCAN_B; off <<= 1) {
        int u = (t >= off) ? sh[t - off] : 0;
        __syncthreads();
        sh[t] += u;
        __syncthreads();
    }
    if (i < N) g_excl[i] = sh[t] - v;
    if (t == SCAN_B - 1) g_bsum[blockIdx.x] = sh[SCAN_B - 1];
}

__global__ void scan2_kernel(int NB, int N) {
    __shared__ int sh[MAX_SCAN_BLOCKS];
    int t = threadIdx.x;
    int v = (t < NB) ? g_bsum[t] : 0;
    sh[t] = v;
    __syncthreads();
#pragma unroll
    for (int off = 1; off < MAX_SCAN_BLOCKS; off <<= 1) {
        int u = (t >= off) ? sh[t - off] : 0;
        __syncthreads();
        sh[t] += u;
        __syncthreads();
    }
    if (t < NB) g_boff[t] = sh[t] - v;
    if (t == MAX_SCAN_BLOCKS - 1) g_start[N] = sh[MAX_SCAN_BLOCKS - 1];
}

// scan3 also re-zeroes g_count for the next graph replay (scan1 already consumed it)
__global__ void scan3_kernel(int N) {
    int i = blockIdx.x * blockDim.x + threadIdx.x;
    if (i < N) {
        int s = g_excl[i] + g_boff[i >> 8];
        g_start[i]  = s;
        g_cursor[i] = s;
        g_count[i]  = 0;
    }
}

__global__ void permute_kernel(const int* __restrict__ src,
                               const int* __restrict__ dst,
                               const float* __restrict__ w,
                               int E) {
    int e = blockIdx.x * blockDim.x + threadIdx.x;
    if (e < E) {
        int pos = atomicAdd(&g_cursor[dst[e]], 1);
        g_edges[pos] = make_int2(src[e], __float_as_int(w[e]));
    }
}

// ---------------------------------------------------------------------------
// Tensor-core GEMM: F' = feature @ W^T, fp16 hi/lo split, fp32 accumulate.
// CTA = 128x128 output tile, 256 thr = 8 warps (4 row-groups x 2 col-groups),
// warp = 32x64 via m16n8k16 (2 m-tiles x 8 n-tiles), K chunked by 32.
// ---------------------------------------------------------------------------
__device__ __forceinline__ uint32_t pack2(__half a, __half b) {
    __half2 h = __halves2half2(a, b);
    return *(uint32_t*)&h;
}

__device__ __forceinline__ void mma16816(float* c, const uint32_t* a,
                                         uint32_t b0, uint32_t b1) {
    asm volatile(
        "mma.sync.aligned.m16n8k16.row.col.f32.f16.f16.f32 "
        "{%0,%1,%2,%3}, {%4,%5,%6,%7}, {%8,%9}, {%0,%1,%2,%3};"
        : "+f"(c[0]), "+f"(c[1]), "+f"(c[2]), "+f"(c[3])
        : "r"(a[0]), "r"(a[1]), "r"(a[2]), "r"(a[3]), "r"(b0), "r"(b1));
}

__global__ void __launch_bounds__(256)
gemm_tc_kernel(const float* __restrict__ A,
               const float* __restrict__ Wm,
               int M) {
    __shared__ uint32_t sAhi[128 * GP];
    __shared__ uint32_t sAlo[128 * GP];
    __shared__ uint32_t sWhi[128 * GP];
    __shared__ uint32_t sWlo[128 * GP];

    int tid  = threadIdx.x;
    int wid  = tid >> 5;
    int lane = tid & 31;
    int wr = (wid & 3) * 32;      // warp row base
    int wc = (wid >> 2) * 64;     // warp col base
    int lr = lane >> 2;           // 0..7
    int lc = lane & 3;            // 0..3
    int br = blockIdx.x * 128;

    float c[2][8][4];
#pragma unroll
    for (int mt = 0; mt < 2; mt++)
#pragma unroll
        for (int nt = 0; nt < 8; nt++)
#pragma unroll
            for (int q = 0; q < 4; q++) c[mt][nt][q] = 0.f;

    for (int kt = 0; kt < D; kt += 32) {
        __syncthreads();
        // fill smem: A and W chunks, 128 rows x 16 half2-pairs each
#pragma unroll
        for (int it = 0; it < 8; it++) {
            int idx = tid + it * 256;     // 0..2047
            int m = idx >> 4;             // row 0..127
            int p = idx & 15;             // pair 0..15

            float2 fa = make_float2(0.f, 0.f);
            if (br + m < M)
                fa = *(const float2*)(A + (size_t)(br + m) * D + kt + p * 2);
            __half hx = __float2half_rn(fa.x);
            __half hy = __float2half_rn(fa.y);
            __half ox = __float2half_rn(fa.x - __half2float(hx));
            __half oy = __float2half_rn(fa.y - __half2float(hy));
            sAhi[m * GP + p] = pack2(hx, hy);
            sAlo[m * GP + p] = pack2(ox, oy);

            float2 fw = *(const float2*)(Wm + (size_t)m * D + kt + p * 2);
            __half wx = __float2half_rn(fw.x);
            __half wy = __float2half_rn(fw.y);
            __half vx = __float2half_rn(fw.x - __half2float(wx));
            __half vy = __float2half_rn(fw.y - __half2float(wy));
            sWhi[m * GP + p] = pack2(wx, wy);
            sWlo[m * GP + p] = pack2(vx, vy);
        }
        __syncthreads();

#pragma unroll
        for (int k2 = 0; k2 < 16; k2 += 8) {   // two k16-steps per chunk
            uint32_t ahi[2][4], alo[2][4];
#pragma unroll
            for (int mt = 0; mt < 2; mt++) {
                int r0 = wr + mt * 16 + lr;
                ahi[mt][0] = sAhi[r0 * GP + k2 + lc];
                ahi[mt][1] = sAhi[(r0 + 8) * GP + k2 + lc];
                ahi[mt][2] = sAhi[r0 * GP + k2 + 4 + lc];
                ahi[mt][3] = sAhi[(r0 + 8) * GP + k2 + 4 + lc];
                alo[mt][0] = sAlo[r0 * GP + k2 + lc];
                alo[mt][1] = sAlo[(r0 + 8) * GP + k2 + lc];
                alo[mt][2] = sAlo[r0 * GP + k2 + 4 + lc];
                alo[mt][3] = sAlo[(r0 + 8) * GP + k2 + 4 + lc];
            }
#pragma unroll
            for (int nt = 0; nt < 8; nt++) {
                int nr = wc + nt * 8 + lr;
                uint32_t bh0 = sWhi[nr * GP + k2 + lc];
                uint32_t bh1 = sWhi[nr * GP + k2 + 4 + lc];
                uint32_t bl0 = sWlo[nr * GP + k2 + lc];
                uint32_t bl1 = sWlo[nr * GP + k2 + 4 + lc];
#pragma unroll
                for (int mt = 0; mt < 2; mt++) {
                    mma16816(c[mt][nt], ahi[mt], bh0, bh1);   // hi*hi
                    mma16816(c[mt][nt], ahi[mt], bl0, bl1);   // hi*lo
                    mma16816(c[mt][nt], alo[mt], bh0, bh1);   // lo*hi
                }
            }
        }
    }

    // store fp16 F'
#pragma unroll
    for (int mt = 0; mt < 2; mt++) {
#pragma unroll
        for (int nt = 0; nt < 8; nt++) {
            int m0  = br + wr + mt * 16 + lr;
            int col = wc + nt * 8 + lc * 2;
            if (m0 < M) {
                __half2 h = __floats2half2_rn(c[mt][nt][0], c[mt][nt][1]);
                *(uint32_t*)(g_fph + (size_t)m0 * D + col) = *(uint32_t*)&h;
            }
            if (m0 + 8 < M) {
                __half2 h = __floats2half2_rn(c[mt][nt][2], c[mt][nt][3]);
                *(uint32_t*)(g_fph + (size_t)(m0 + 8) * D + col) = *(uint32_t*)&h;
            }
        }
    }
}

// ---------------------------------------------------------------------------
// Aggregate + epilogue (unchanged from R10): warp/node, fp16 rows, fp32 accum
// ---------------------------------------------------------------------------
__global__ void aggregate_out_kernel(const float* __restrict__ bias,
                                     float* __restrict__ out,
                                     int N) {
    int t = blockIdx.x * blockDim.x + threadIdx.x;
    int n = t >> 5;
    if (n >= N) return;
    int lane = t & 31;
    int col = lane * 4;

    int beg = g_start[n];
    int end = g_start[n + 1];

    float4 acc = make_float4(0.f, 0.f, 0.f, 0.f);
    int i = beg;
    for (; i + 3 < end; i += 4) {
        int2 p0 = __ldg(&g_edges[i]);
        int2 p1 = __ldg(&g_edges[i + 1]);
        int2 p2 = __ldg(&g_edges[i + 2]);
        int2 p3 = __ldg(&g_edges[i + 3]);
        uint2 u0 = *(const uint2*)(g_fph + (size_t)p0.x * D + col);
        uint2 u1 = *(const uint2*)(g_fph + (size_t)p1.x * D + col);
        uint2 u2 = *(const uint2*)(g_fph + (size_t)p2.x * D + col);
        uint2 u3 = *(const uint2*)(g_fph + (size_t)p3.x * D + col);
        float w0 = __int_as_float(p0.y);
        float w1 = __int_as_float(p1.y);
        float w2 = __int_as_float(p2.y);
        float w3 = __int_as_float(p3.y);

        float2 a0 = __half22float2(*(__half2*)&u0.x), b0 = __half22float2(*(__half2*)&u0.y);
        float2 a1 = __half22float2(*(__half2*)&u1.x), b1 = __half22float2(*(__half2*)&u1.y);
        float2 a2 = __half22float2(*(__half2*)&u2.x), b2 = __half22float2(*(__half2*)&u2.y);
        float2 a3 = __half22float2(*(__half2*)&u3.x), b3 = __half22float2(*(__half2*)&u3.y);

        acc.x += a0.x * w0 + a1.x * w1 + a2.x * w2 + a3.x * w3;
        acc.y += a0.y * w0 + a1.y * w1 + a2.y * w2 + a3.y * w3;
        acc.z += b0.x * w0 + b1.x * w1 + b2.x * w2 + b3.x * w3;
        acc.w += b0.y * w0 + b1.y * w1 + b2.y * w2 + b3.y * w3;
    }
    for (; i < end; i++) {
        int2 p0 = __ldg(&g_edges[i]);
        uint2 u0 = *(const uint2*)(g_fph + (size_t)p0.x * D + col);
        float w0 = __int_as_float(p0.y);
        float2 a0 = __half22float2(*(__half2*)&u0.x), b0 = __half22float2(*(__half2*)&u0.y);
        acc.x += a0.x * w0;
        acc.y += a0.y * w0;
        acc.z += b0.x * w0;
        acc.w += b0.y * w0;
    }

    float4 b4 = __ldg((const float4*)(bias + col));
    acc.x = fmaxf(acc.x + b4.x, 0.f);
    acc.y = fmaxf(acc.y + b4.y, 0.f);
    acc.z = fmaxf(acc.z + b4.z, 0.f);
    acc.w = fmaxf(acc.w + b4.w, 0.f);

    *(float4*)(out + (size_t)n * D + col) = acc;
}

// ---------------------------------------------------------------------------
// Launch: fork-join (R8 structure), zero kernel removed (folded into scan3)
// ---------------------------------------------------------------------------
extern "C" void kernel_launch(void* const* d_in, const int* in_sizes, int n_in,
                              void* d_out, int out_size) {
    const float* feature = (const float*)d_in[0];
    const int*   src     = (const int*)d_in[1];
    const int*   dst     = (const int*)d_in[2];
    const float* w       = (const float*)d_in[3];
    const float* Wm      = (const float*)d_in[4];
    const float* bias    = (const float*)d_in[5];
    float*       out     = (float*)d_out;

    int M = in_sizes[0] / D;
    int E = in_sizes[1];
    if (E > MAX_E) E = MAX_E;

    static cudaStream_t s2 = nullptr;
    static cudaEvent_t evFork = nullptr, evGemm = nullptr;
    if (s2 == nullptr) {
        cudaStreamCreateWithFlags(&s2, cudaStreamNonBlocking);
        cudaEventCreateWithFlags(&evFork, cudaEventDisableTiming);
        cudaEventCreateWithFlags(&evGemm, cudaEventDisableTiming);
    }

    // Fork: tensor-core GEMM on side stream
    cudaEventRecord(evFork, 0);
    cudaStreamWaitEvent(s2, evFork, 0);
    gemm_tc_kernel<<<(M + 127) / 128, 256, 0, s2>>>(feature, Wm, M);
    cudaEventRecord(evGemm, s2);

    // Main stream: binning chain
    int NB = (M + SCAN_B - 1) / SCAN_B;
    hist_kernel<<<(E + 255) / 256, 256>>>(dst, E);
    scan1_kernel<<<NB, SCAN_B>>>(M);
    scan2_kernel<<<1, MAX_SCAN_BLOCKS>>>(NB, M);
    scan3_kernel<<<(M + 255) / 256, 256>>>(M);
    permute_kernel<<<(E + 255) / 256, 256>>>(src, dst, w, E);

    // Join, then aggregate + epilogue
    cudaStreamWaitEvent(0, evGemm, 0);
    long long agg_threads = (long long)M * 32;
    aggregate_out_kernel<<<(int)((agg_threads + 255) / 256), 256>>>(bias, out, M);
}